// round 10
// baseline (speedup 1.0000x reference)
#include <cuda_runtime.h>
#include <cuda_bf16.h>
#include <cstdint>

// Problem constants
#define NN 8192
#define RR 32
#define TN 128                    // M-tile per block
#define SPLITK 32
#define KCHUNK (NN / SPLITK)      // 256
#define NSTG32 (KCHUNK / 32)      // 8 k32 stages

// Scratch
__device__ float g_z[4 * RR * NN];          // z stages [k][r][n]
__device__ float g_part[SPLITK * RR * NN];  // split-K partials (32 MB)

// B smem: hi/lo bf16, [32 rows][256 k], row = 512B, XOR-16B swizzle by (n&7)
#define BROW_BYTES 512

__device__ __forceinline__ uint32_t cvt_bf16x2(float hi, float lo) {
    uint32_t r;
    asm("cvt.rn.bf16x2.f32 %0,%1,%2;" : "=r"(r) : "f"(hi), "f"(lo));
    return r;
}
// split 2 fp32 -> packed bf16 hi-pair and lo-pair (element x in low half)
__device__ __forceinline__ void split2(float x, float y, uint32_t& w, uint32_t& l) {
    w = cvt_bf16x2(y, x);
    float h0 = __uint_as_float(w << 16);
    float h1 = __uint_as_float(w & 0xFFFF0000u);
    l = cvt_bf16x2(y - h1, x - h0);
}
__device__ __forceinline__ void ldsm4(uint32_t& r0, uint32_t& r1, uint32_t& r2,
                                      uint32_t& r3, uint32_t a) {
    asm volatile("ldmatrix.sync.aligned.m8n8.x4.shared.b16 {%0,%1,%2,%3},[%4];"
                 : "=r"(r0), "=r"(r1), "=r"(r2), "=r"(r3) : "r"(a));
}
__device__ __forceinline__ void mma16816(float& c0, float& c1, float& c2, float& c3,
                                         uint32_t a0, uint32_t a1, uint32_t a2, uint32_t a3,
                                         uint32_t b0, uint32_t b1) {
    asm volatile(
        "mma.sync.aligned.m16n8k16.row.col.f32.bf16.bf16.f32 "
        "{%0,%1,%2,%3},{%4,%5,%6,%7},{%8,%9},{%0,%1,%2,%3};"
        : "+f"(c0), "+f"(c1), "+f"(c2), "+f"(c3)
        : "r"(a0), "r"(a1), "r"(a2), "r"(a3), "r"(b0), "r"(b1));
}
__device__ __forceinline__ void cp16(uint32_t dst, const void* src) {
    asm volatile("cp.async.cg.shared.global [%0], [%1], 16;" :: "r"(dst), "l"(src));
}
__device__ __forceinline__ float2 lds64(uint32_t addr) {
    float2 v;
    asm volatile("ld.shared.v2.f32 {%0,%1},[%2];" : "=f"(v.x), "=f"(v.y) : "r"(addr));
    return v;
}

// ---------------------------------------------------------------------------
// Stage 0: transpose x[B,N,G] -> z0[r][n], r = b*8+g
// ---------------------------------------------------------------------------
__global__ void transpose_kernel(const float* __restrict__ x, float* __restrict__ z0) {
    int idx = blockIdx.x * 256 + threadIdx.x;
    int n = idx & (NN - 1);
    int r = idx >> 13;
    int b = r >> 3;
    int g = r & 7;
    z0[idx] = x[((b << 13) + n) * 8 + g];
}

// ---------------------------------------------------------------------------
// bf16x3 mma.sync GEMM:
//   part[sp][r][n0+m] = sum_{k in chunk} S[n0+m][k] * z[r][k]
// A staged through smem via cp.async at k32 granularity (full-128B-line
// fetches), fragments read with swizzled LDS.64 and converted in-register.
// B pre-split into bf16 hi/lo smem once per CTA (proven R8 path).
// ---------------------------------------------------------------------------
__global__ void __launch_bounds__(256, 4)
gemm_kernel(const float* __restrict__ A, const float* __restrict__ B,
            float* __restrict__ part) {
    __shared__ __align__(128) float smA[TN * 32];            // 16 KB (one k32 stage)
    __shared__ __align__(128) char smBH[RR * BROW_BYTES];    // 16 KB
    __shared__ __align__(128) char smBL[RR * BROW_BYTES];    // 16 KB

    const int tid = threadIdx.x;
    const int wid = tid >> 5;
    const int lid = tid & 31;
    const int nb  = blockIdx.x;   // 0..63
    const int sp  = blockIdx.y;   // 0..SPLITK-1
    const int n0  = nb * TN;
    const int m0  = sp * KCHUNK;

    const uint32_t smA_u = (uint32_t)__cvta_generic_to_shared(smA);

    // ---------------- A cp.async mapping (full-line, swizzled dst) ----------
    const int ar = tid >> 3;              // 0..31
    const int ac = tid & 7;               // 16B chunk within 128B row
    const float* Asrc = A + (size_t)(n0 + ar) * NN + m0 + ac * 4;
    const uint32_t a_sw = ((uint32_t)(ac ^ (ar & 7))) << 4;
    uint32_t adst[4];
#pragma unroll
    for (int p = 0; p < 4; p++)
        adst[p] = smA_u + (uint32_t)(ar + 32 * p) * 128u + a_sw;

    // issue stage 0 immediately (before B staging) to get DRAM going
#pragma unroll
    for (int p = 0; p < 4; p++)
        cp16(adst[p], Asrc + (size_t)(32 * p) * NN);
    asm volatile("cp.async.commit_group;");

    // ---------------- one-time B staging: fp32 -> bf16 hi/lo smem ----------
    {
        const int row   = tid >> 3;          // 0..31
        const int kbase = (tid & 7) << 3;    // 0..56 step 8
        const float* bp = B + (size_t)row * NN + m0 + kbase;
        const uint32_t ph = ((uint32_t)row & 7u) << 4;   // 16B-granule XOR phase
#pragma unroll
        for (int i = 0; i < 4; i++) {
            const int k = kbase + 64 * i;
            float4 v0 = *(const float4*)(bp + 64 * i);
            float4 v1 = *(const float4*)(bp + 64 * i + 4);
            uint32_t h0, l0, h1, l1, h2, l2, h3, l3;
            split2(v0.x, v0.y, h0, l0);
            split2(v0.z, v0.w, h1, l1);
            split2(v1.x, v1.y, h2, l2);
            split2(v1.z, v1.w, h3, l3);
            uint32_t off = (uint32_t)row * BROW_BYTES + (((uint32_t)k * 2u) ^ ph);
            *(uint4*)(smBH + off) = make_uint4(h0, h1, h2, h3);
            *(uint4*)(smBL + off) = make_uint4(l0, l1, l2, l3);
        }
    }
    __syncthreads();   // B visible (A stage-0 handled by wait_group below)

    // ---------------- fragment lane mappings --------------------------------
    const int rg = lid >> 2;            // 0..7
    const int qh = (lid & 3) >> 1;      // q>>1
    const uint32_t qb = (uint32_t)(lid & 1) * 8u;   // (q&1)*8
    const uint32_t a_row_off = smA_u + (uint32_t)(16 * wid + rg) * 128u;

    // B ldmatrix (verified): brow/bhalf lane mapping
    const int brow0 = ((lid >> 4) << 3) + (lid & 7);   // n-tiles 0/1
    const int brow1 = 16 + brow0;                      // n-tiles 2/3
    const int bhalf = (lid >> 3) & 1;
    const uint32_t smbh = (uint32_t)__cvta_generic_to_shared(smBH);
    const uint32_t smbl = (uint32_t)__cvta_generic_to_shared(smBL);
    const uint32_t bo0base = (uint32_t)brow0 * BROW_BYTES;
    const uint32_t bo1base = (uint32_t)brow1 * BROW_BYTES;
    const uint32_t bph0 = ((uint32_t)brow0 & 7u) << 4;
    const uint32_t bph1 = ((uint32_t)brow1 & 7u) << 4;

    float c[4][4];
#pragma unroll
    for (int j = 0; j < 4; j++)
#pragma unroll
        for (int e = 0; e < 4; e++) c[j][e] = 0.0f;

#pragma unroll
    for (int s = 0; s < NSTG32; s++) {
        asm volatile("cp.async.wait_group 0;" ::: "memory");
        __syncthreads();   // all threads' A(s) copies landed

        // compute the two k16 halves of this k32 stage
#pragma unroll
        for (int h = 0; h < 2; h++) {
            // A fragments via swizzled LDS.64 (granule g = h*4 (+2) + qh, XOR rg)
            const uint32_t g0 = (uint32_t)(h * 4 + qh);
            const uint32_t g2 = g0 + 2u;
            float2 fa0 = lds64(a_row_off + ((g0 ^ (uint32_t)rg) << 4) + qb);
            float2 fa1 = lds64(a_row_off + 8u * 128u + ((g0 ^ (uint32_t)rg) << 4) + qb);
            float2 fa2 = lds64(a_row_off + ((g2 ^ (uint32_t)rg) << 4) + qb);
            float2 fa3 = lds64(a_row_off + 8u * 128u + ((g2 ^ (uint32_t)rg) << 4) + qb);

            // B fragments from smem (hi + lo), swizzled ldmatrix
            const uint32_t kb = (uint32_t)((2 * s + h) * 32 + bhalf * 16);
            const uint32_t o0 = bo0base + (kb ^ bph0);
            const uint32_t o1 = bo1base + (kb ^ bph1);
            uint32_t bh[8], bl[8];
            ldsm4(bh[0], bh[1], bh[2], bh[3], smbh + o0);
            ldsm4(bh[4], bh[5], bh[6], bh[7], smbh + o1);
            ldsm4(bl[0], bl[1], bl[2], bl[3], smbl + o0);
            ldsm4(bl[4], bl[5], bl[6], bl[7], smbl + o1);

            // A convert
            uint32_t ah[4], al[4];
            split2(fa0.x, fa0.y, ah[0], al[0]);
            split2(fa1.x, fa1.y, ah[1], al[1]);
            split2(fa2.x, fa2.y, ah[2], al[2]);
            split2(fa3.x, fa3.y, ah[3], al[3]);

            // 12 MMAs: hi*hi + hi*lo + lo*hi
#pragma unroll
            for (int j = 0; j < 4; j++) {
                mma16816(c[j][0], c[j][1], c[j][2], c[j][3],
                         ah[0], ah[1], ah[2], ah[3], bh[2 * j], bh[2 * j + 1]);
                mma16816(c[j][0], c[j][1], c[j][2], c[j][3],
                         ah[0], ah[1], ah[2], ah[3], bl[2 * j], bl[2 * j + 1]);
                mma16816(c[j][0], c[j][1], c[j][2], c[j][3],
                         al[0], al[1], al[2], al[3], bh[2 * j], bh[2 * j + 1]);
            }
        }

        __syncthreads();   // everyone done reading A(s) before overwrite

        if (s + 1 < NSTG32) {
            const float* src = Asrc + (s + 1) * 32;
#pragma unroll
            for (int p = 0; p < 4; p++)
                cp16(adst[p], src + (size_t)(32 * p) * NN);
            asm volatile("cp.async.commit_group;");
        }
    }

    // epilogue: thread holds (m = 16w + rg (+8), n = 8j + kc (+1)), kc=2*(lid&3)
    const int kc = (lid & 3) << 1;
    const int mg = n0 + 16 * wid + rg;
#pragma unroll
    for (int j = 0; j < 4; j++) {
        int r = 8 * j + kc;
        float* p0 = part + (size_t)(sp * RR + r) * NN + mg;
        float* p1 = part + (size_t)(sp * RR + r + 1) * NN + mg;
        p0[0] = c[j][0];
        p1[0] = c[j][1];
        p0[8] = c[j][2];
        p1[8] = c[j][3];
    }
}

// ---------------------------------------------------------------------------
// Reduce split-K partials into next z stage
// ---------------------------------------------------------------------------
__global__ void reduce_kernel(const float* __restrict__ part, float* __restrict__ out) {
    int idx = blockIdx.x * 256 + threadIdx.x;   // over 65536 float4
    const float4* p4 = (const float4*)part;
    float4 s = p4[idx];
#pragma unroll
    for (int sI = 1; sI < SPLITK; sI++) {
        float4 t = p4[idx + sI * (RR * NN / 4)];
        s.x += t.x; s.y += t.y; s.z += t.z; s.w += t.w;
    }
    ((float4*)out)[idx] = s;
}

// ---------------------------------------------------------------------------
// Final projection (torch-faithful raw-reshape mapping)
// ---------------------------------------------------------------------------
__global__ void final_kernel(const float* __restrict__ z, const float* __restrict__ W,
                             const float* __restrict__ bias, float* __restrict__ y) {
    __shared__ float Ws[256];
    __shared__ float bs[8];
    int t = threadIdx.x;
    Ws[t] = W[t];
    if (t < 8) bs[t] = bias[t];
    __syncthreads();

    int idx = blockIdx.x * 256 + t;
    int n = idx & (NN - 1);
    int b = idx >> 13;
    int k0 = n >> 11;
    int g0 = (n >> 8) & 7;
    const float* zp = z + ((size_t)(k0 * RR + b * 8 + g0) << 13) + ((n & 255) << 5);

    float bb = bs[n >> 10];
    float acc[8];
#pragma unroll
    for (int f = 0; f < 8; f++) acc[f] = bb;

#pragma unroll
    for (int jq = 0; jq < 8; jq++) {
        float4 zv = *(const float4*)(zp + 4 * jq);
#pragma unroll
        for (int e = 0; e < 4; e++) {
            float zs = (e == 0) ? zv.x : (e == 1) ? zv.y : (e == 2) ? zv.z : zv.w;
            int j = 4 * jq + e;
#pragma unroll
            for (int f = 0; f < 8; f++) acc[f] += zs * Ws[8 * j + f];
        }
    }

    float4* yo = (float4*)(y + (size_t)idx * 8);
    yo[0] = make_float4(acc[0], acc[1], acc[2], acc[3]);
    yo[1] = make_float4(acc[4], acc[5], acc[6], acc[7]);
}

// ---------------------------------------------------------------------------
extern "C" void kernel_launch(void* const* d_in, const int* in_sizes, int n_in,
                              void* d_out, int out_size) {
    const float* x    = (const float*)d_in[0];
    const float* S    = (const float*)d_in[1];
    const float* W    = (const float*)d_in[2];
    const float* bias = (const float*)d_in[3];
    float* y = (float*)d_out;

    float *zbuf, *pbuf;
    cudaGetSymbolAddress((void**)&zbuf, g_z);
    cudaGetSymbolAddress((void**)&pbuf, g_part);

    transpose_kernel<<<1024, 256>>>(x, zbuf);

    for (int k = 0; k < 3; k++) {
        gemm_kernel<<<dim3(64, SPLITK), 256>>>(S + (size_t)k * NN * NN,
                                               zbuf + (size_t)k * RR * NN, pbuf);
        reduce_kernel<<<256, 256>>>(pbuf, zbuf + (size_t)(k + 1) * RR * NN);
    }

    final_kernel<<<128, 256>>>(zbuf, W, bias, y);
}

// round 11
// speedup vs baseline: 1.2180x; 1.2180x over previous
#include <cuda_runtime.h>
#include <cuda_bf16.h>
#include <cstdint>

// Problem constants
#define NN 8192
#define RR 32
#define TN 128                    // M-tile per block
#define SPLITK 64
#define KCHUNK (NN / SPLITK)      // 128
#define NSTG32 (KCHUNK / 32)      // 4 k32 stages

// Scratch: z stages only (partials now atomically reduced into z directly)
__device__ float g_z[4 * RR * NN];          // z stages [k][r][n]

// B smem row: 128 k * 2B = 256 bytes, XOR-16B swizzle by (row&7)
#define BROW_BYTES 256
#define A_STAGE_FLOATS (TN * 32)   // 16 KB per buffer

__device__ __forceinline__ uint32_t cvt_bf16x2(float hi, float lo) {
    uint32_t r;
    asm("cvt.rn.bf16x2.f32 %0,%1,%2;" : "=r"(r) : "f"(hi), "f"(lo));
    return r;
}
// split 2 fp32 -> packed bf16 hi-pair and lo-pair (element x in low half)
__device__ __forceinline__ void split2(float x, float y, uint32_t& w, uint32_t& l) {
    w = cvt_bf16x2(y, x);
    float h0 = __uint_as_float(w << 16);
    float h1 = __uint_as_float(w & 0xFFFF0000u);
    l = cvt_bf16x2(y - h1, x - h0);
}
__device__ __forceinline__ void ldsm4(uint32_t& r0, uint32_t& r1, uint32_t& r2,
                                      uint32_t& r3, uint32_t a) {
    asm volatile("ldmatrix.sync.aligned.m8n8.x4.shared.b16 {%0,%1,%2,%3},[%4];"
                 : "=r"(r0), "=r"(r1), "=r"(r2), "=r"(r3) : "r"(a));
}
__device__ __forceinline__ void mma16816(float& c0, float& c1, float& c2, float& c3,
                                         uint32_t a0, uint32_t a1, uint32_t a2, uint32_t a3,
                                         uint32_t b0, uint32_t b1) {
    asm volatile(
        "mma.sync.aligned.m16n8k16.row.col.f32.bf16.bf16.f32 "
        "{%0,%1,%2,%3},{%4,%5,%6,%7},{%8,%9},{%0,%1,%2,%3};"
        : "+f"(c0), "+f"(c1), "+f"(c2), "+f"(c3)
        : "r"(a0), "r"(a1), "r"(a2), "r"(a3), "r"(b0), "r"(b1));
}
__device__ __forceinline__ void cp16(uint32_t dst, const void* src) {
    asm volatile("cp.async.cg.shared.global [%0], [%1], 16;" :: "r"(dst), "l"(src));
}
__device__ __forceinline__ float2 lds64(uint32_t addr) {
    float2 v;
    asm volatile("ld.shared.v2.f32 {%0,%1},[%2];" : "=f"(v.x), "=f"(v.y) : "r"(addr));
    return v;
}

// ---------------------------------------------------------------------------
// Stage 0: transpose x[B,N,G] -> z0[r][n], r = b*8+g
// ---------------------------------------------------------------------------
__global__ void transpose_kernel(const float* __restrict__ x, float* __restrict__ z0) {
    int idx = blockIdx.x * 256 + threadIdx.x;
    int n = idx & (NN - 1);
    int r = idx >> 13;
    int b = r >> 3;
    int g = r & 7;
    z0[idx] = x[((b << 13) + n) * 8 + g];
}

// ---------------------------------------------------------------------------
// Zero-fill z stages 1..3 (atomic accumulation targets)
// ---------------------------------------------------------------------------
__global__ void zero_kernel(float* __restrict__ p) {
    ((float4*)p)[blockIdx.x * 256 + threadIdx.x] = make_float4(0.f, 0.f, 0.f, 0.f);
}

// ---------------------------------------------------------------------------
// bf16x3 mma.sync GEMM with atomic split-K epilogue:
//   zn[r][n0+m] += sum_{k in chunk sp} S[n0+m][k] * z[r][k]
// A double-buffered through smem via cp.async (full 128B lines), prefetch
// overlaps compute; B pre-split to bf16 hi/lo smem once per CTA.
// ---------------------------------------------------------------------------
__global__ void __launch_bounds__(256, 4)
gemm_kernel(const float* __restrict__ A, const float* __restrict__ B,
            float* __restrict__ zn) {
    __shared__ __align__(128) float smA[2][A_STAGE_FLOATS];  // 32 KB
    __shared__ __align__(128) char smBH[RR * BROW_BYTES];    // 8 KB
    __shared__ __align__(128) char smBL[RR * BROW_BYTES];    // 8 KB

    const int tid = threadIdx.x;
    const int wid = tid >> 5;
    const int lid = tid & 31;
    const int nb  = blockIdx.x;   // 0..63
    const int sp  = blockIdx.y;   // 0..SPLITK-1
    const int n0  = nb * TN;
    const int m0  = sp * KCHUNK;

    const uint32_t smA_u = (uint32_t)__cvta_generic_to_shared(&smA[0][0]);

    // ---------------- A cp.async mapping (full-line, swizzled dst) ----------
    const int ar = tid >> 3;              // 0..31
    const int ac = tid & 7;               // 16B chunk within 128B row
    const float* Asrc = A + (size_t)(n0 + ar) * NN + m0 + ac * 4;
    const uint32_t a_sw = ((uint32_t)(ac ^ (ar & 7))) << 4;
    uint32_t adst[4];
#pragma unroll
    for (int p = 0; p < 4; p++)
        adst[p] = smA_u + (uint32_t)(ar + 32 * p) * 128u + a_sw;

    // prologue: issue stage 0 into buffer 0 (DRAM starts while we stage B)
#pragma unroll
    for (int p = 0; p < 4; p++)
        cp16(adst[p], Asrc + (size_t)(32 * p) * NN);
    asm volatile("cp.async.commit_group;");

    // ---------------- one-time B staging: fp32 -> bf16 hi/lo smem ----------
    {
        const int row   = tid >> 3;          // 0..31
        const int kbase = (tid & 7) << 3;    // 0..56 step 8
        const float* bp = B + (size_t)row * NN + m0 + kbase;
        const uint32_t ph = ((uint32_t)row & 7u) << 4;   // 16B-granule XOR phase
#pragma unroll
        for (int i = 0; i < 2; i++) {
            const int k = kbase + 64 * i;
            float4 v0 = *(const float4*)(bp + 64 * i);
            float4 v1 = *(const float4*)(bp + 64 * i + 4);
            uint32_t h0, l0, h1, l1, h2, l2, h3, l3;
            split2(v0.x, v0.y, h0, l0);
            split2(v0.z, v0.w, h1, l1);
            split2(v1.x, v1.y, h2, l2);
            split2(v1.z, v1.w, h3, l3);
            uint32_t off = (uint32_t)row * BROW_BYTES + (((uint32_t)k * 2u) ^ ph);
            *(uint4*)(smBH + off) = make_uint4(h0, h1, h2, h3);
            *(uint4*)(smBL + off) = make_uint4(l0, l1, l2, l3);
        }
    }

    // ---------------- fragment lane mappings --------------------------------
    const int rg = lid >> 2;            // 0..7
    const int qh = (lid & 3) >> 1;      // q>>1
    const uint32_t qb = (uint32_t)(lid & 1) * 8u;   // (q&1)*8

    const int brow0 = ((lid >> 4) << 3) + (lid & 7);   // n-tiles 0/1
    const int brow1 = 16 + brow0;                      // n-tiles 2/3
    const int bhalf = (lid >> 3) & 1;
    const uint32_t smbh = (uint32_t)__cvta_generic_to_shared(smBH);
    const uint32_t smbl = (uint32_t)__cvta_generic_to_shared(smBL);
    const uint32_t bo0base = (uint32_t)brow0 * BROW_BYTES;
    const uint32_t bo1base = (uint32_t)brow1 * BROW_BYTES;
    const uint32_t bph0 = ((uint32_t)brow0 & 7u) << 4;
    const uint32_t bph1 = ((uint32_t)brow1 & 7u) << 4;

    float c[4][4];
#pragma unroll
    for (int j = 0; j < 4; j++)
#pragma unroll
        for (int e = 0; e < 4; e++) c[j][e] = 0.0f;

#pragma unroll
    for (int s = 0; s < NSTG32; s++) {
        const uint32_t abuf = smA_u + (uint32_t)(s & 1) * (A_STAGE_FLOATS * 4);

        asm volatile("cp.async.wait_group 0;" ::: "memory");
        __syncthreads();   // A(s) visible everywhere; stage s-1 compute done

        // prefetch A(s+1) into the other buffer — overlaps compute below
        if (s + 1 < NSTG32) {
            const float* src = Asrc + (s + 1) * 32;
            const uint32_t obuf = (uint32_t)((s + 1) & 1) * (A_STAGE_FLOATS * 4);
#pragma unroll
            for (int p = 0; p < 4; p++)
                cp16(adst[p] + obuf, src + (size_t)(32 * p) * NN);
            asm volatile("cp.async.commit_group;");
        }

        const uint32_t a_row_off = abuf + (uint32_t)(16 * wid + rg) * 128u;

        // compute the two k16 halves of this k32 stage
#pragma unroll
        for (int h = 0; h < 2; h++) {
            const uint32_t g0 = (uint32_t)(h * 4 + qh);
            const uint32_t g2 = g0 + 2u;
            float2 fa0 = lds64(a_row_off + ((g0 ^ (uint32_t)rg) << 4) + qb);
            float2 fa1 = lds64(a_row_off + 8u * 128u + ((g0 ^ (uint32_t)rg) << 4) + qb);
            float2 fa2 = lds64(a_row_off + ((g2 ^ (uint32_t)rg) << 4) + qb);
            float2 fa3 = lds64(a_row_off + 8u * 128u + ((g2 ^ (uint32_t)rg) << 4) + qb);

            const uint32_t kb = (uint32_t)((2 * s + h) * 32 + bhalf * 16);
            const uint32_t o0 = bo0base + (kb ^ bph0);
            const uint32_t o1 = bo1base + (kb ^ bph1);
            uint32_t bh[8], bl[8];
            ldsm4(bh[0], bh[1], bh[2], bh[3], smbh + o0);
            ldsm4(bh[4], bh[5], bh[6], bh[7], smbh + o1);
            ldsm4(bl[0], bl[1], bl[2], bl[3], smbl + o0);
            ldsm4(bl[4], bl[5], bl[6], bl[7], smbl + o1);

            uint32_t ah[4], al[4];
            split2(fa0.x, fa0.y, ah[0], al[0]);
            split2(fa1.x, fa1.y, ah[1], al[1]);
            split2(fa2.x, fa2.y, ah[2], al[2]);
            split2(fa3.x, fa3.y, ah[3], al[3]);

#pragma unroll
            for (int j = 0; j < 4; j++) {
                mma16816(c[j][0], c[j][1], c[j][2], c[j][3],
                         ah[0], ah[1], ah[2], ah[3], bh[2 * j], bh[2 * j + 1]);
                mma16816(c[j][0], c[j][1], c[j][2], c[j][3],
                         ah[0], ah[1], ah[2], ah[3], bl[2 * j], bl[2 * j + 1]);
                mma16816(c[j][0], c[j][1], c[j][2], c[j][3],
                         al[0], al[1], al[2], al[3], bh[2 * j], bh[2 * j + 1]);
            }
        }
    }

    // atomic split-K epilogue: accumulate into zn[r][n]
    const int kc = (lid & 3) << 1;
    const int mg = n0 + 16 * wid + rg;
#pragma unroll
    for (int j = 0; j < 4; j++) {
        int r = 8 * j + kc;
        float* p0 = zn + (size_t)r * NN + mg;
        float* p1 = zn + (size_t)(r + 1) * NN + mg;
        atomicAdd(p0, c[j][0]);
        atomicAdd(p1, c[j][1]);
        atomicAdd(p0 + 8, c[j][2]);
        atomicAdd(p1 + 8, c[j][3]);
    }
}

// ---------------------------------------------------------------------------
// Final projection (torch-faithful raw-reshape mapping)
// ---------------------------------------------------------------------------
__global__ void final_kernel(const float* __restrict__ z, const float* __restrict__ W,
                             const float* __restrict__ bias, float* __restrict__ y) {
    __shared__ float Ws[256];
    __shared__ float bs[8];
    int t = threadIdx.x;
    Ws[t] = W[t];
    if (t < 8) bs[t] = bias[t];
    __syncthreads();

    int idx = blockIdx.x * 256 + t;
    int n = idx & (NN - 1);
    int b = idx >> 13;
    int k0 = n >> 11;
    int g0 = (n >> 8) & 7;
    const float* zp = z + ((size_t)(k0 * RR + b * 8 + g0) << 13) + ((n & 255) << 5);

    float bb = bs[n >> 10];
    float acc[8];
#pragma unroll
    for (int f = 0; f < 8; f++) acc[f] = bb;

#pragma unroll
    for (int jq = 0; jq < 8; jq++) {
        float4 zv = *(const float4*)(zp + 4 * jq);
#pragma unroll
        for (int e = 0; e < 4; e++) {
            float zs = (e == 0) ? zv.x : (e == 1) ? zv.y : (e == 2) ? zv.z : zv.w;
            int j = 4 * jq + e;
#pragma unroll
            for (int f = 0; f < 8; f++) acc[f] += zs * Ws[8 * j + f];
        }
    }

    float4* yo = (float4*)(y + (size_t)idx * 8);
    yo[0] = make_float4(acc[0], acc[1], acc[2], acc[3]);
    yo[1] = make_float4(acc[4], acc[5], acc[6], acc[7]);
}

// ---------------------------------------------------------------------------
extern "C" void kernel_launch(void* const* d_in, const int* in_sizes, int n_in,
                              void* d_out, int out_size) {
    const float* x    = (const float*)d_in[0];
    const float* S    = (const float*)d_in[1];
    const float* W    = (const float*)d_in[2];
    const float* bias = (const float*)d_in[3];
    float* y = (float*)d_out;

    float* zbuf;
    cudaGetSymbolAddress((void**)&zbuf, g_z);

    transpose_kernel<<<1024, 256>>>(x, zbuf);
    // zero z stages 1..3 (3 * RR * NN floats = 196608 float4)
    zero_kernel<<<768, 256>>>(zbuf + RR * NN);

    for (int k = 0; k < 3; k++) {
        gemm_kernel<<<dim3(64, SPLITK), 256>>>(S + (size_t)k * NN * NN,
                                               zbuf + (size_t)k * RR * NN,
                                               zbuf + (size_t)(k + 1) * RR * NN);
    }

    final_kernel<<<128, 256>>>(zbuf, W, bias, y);
}

// round 12
// speedup vs baseline: 1.3273x; 1.0897x over previous
#include <cuda_runtime.h>
#include <cuda_bf16.h>
#include <cstdint>

// Problem constants
#define NN 8192
#define RR 32
#define TN 128                    // M-tile per block
#define SPLITK 64
#define KCHUNK (NN / SPLITK)      // 128
#define NSTG16 (KCHUNK / 16)      // 8 k16 stages
#define NBUF 4                    // A ring buffers

// Scratch: z stages only (split-K reduced atomically into z)
__device__ float g_z[4 * RR * NN];          // z stages [k][r][n]

// B smem row: 128 k * 2B = 256 bytes, XOR-16B swizzle by (row&7)
#define BROW_BYTES 256
#define A_STAGE_BYTES (TN * 64)   // 8 KB per k16 buffer

__device__ __forceinline__ uint32_t cvt_bf16x2(float hi, float lo) {
    uint32_t r;
    asm("cvt.rn.bf16x2.f32 %0,%1,%2;" : "=r"(r) : "f"(hi), "f"(lo));
    return r;
}
// split 2 fp32 -> packed bf16 hi-pair and lo-pair (element x in low half)
__device__ __forceinline__ void split2(float x, float y, uint32_t& w, uint32_t& l) {
    w = cvt_bf16x2(y, x);
    float h0 = __uint_as_float(w << 16);
    float h1 = __uint_as_float(w & 0xFFFF0000u);
    l = cvt_bf16x2(y - h1, x - h0);
}
__device__ __forceinline__ void ldsm4(uint32_t& r0, uint32_t& r1, uint32_t& r2,
                                      uint32_t& r3, uint32_t a) {
    asm volatile("ldmatrix.sync.aligned.m8n8.x4.shared.b16 {%0,%1,%2,%3},[%4];"
                 : "=r"(r0), "=r"(r1), "=r"(r2), "=r"(r3) : "r"(a));
}
__device__ __forceinline__ void mma16816(float& c0, float& c1, float& c2, float& c3,
                                         uint32_t a0, uint32_t a1, uint32_t a2, uint32_t a3,
                                         uint32_t b0, uint32_t b1) {
    asm volatile(
        "mma.sync.aligned.m16n8k16.row.col.f32.bf16.bf16.f32 "
        "{%0,%1,%2,%3},{%4,%5,%6,%7},{%8,%9},{%0,%1,%2,%3};"
        : "+f"(c0), "+f"(c1), "+f"(c2), "+f"(c3)
        : "r"(a0), "r"(a1), "r"(a2), "r"(a3), "r"(b0), "r"(b1));
}
__device__ __forceinline__ void cp16(uint32_t dst, const void* src) {
    asm volatile("cp.async.cg.shared.global [%0], [%1], 16;" :: "r"(dst), "l"(src));
}
__device__ __forceinline__ float2 lds64(uint32_t addr) {
    float2 v;
    asm volatile("ld.shared.v2.f32 {%0,%1},[%2];" : "=f"(v.x), "=f"(v.y) : "r"(addr));
    return v;
}

// ---------------------------------------------------------------------------
// Stage 0: transpose x[B,N,G] -> z0[r][n], r = b*8+g
// ---------------------------------------------------------------------------
__global__ void transpose_kernel(const float* __restrict__ x, float* __restrict__ z0) {
    int idx = blockIdx.x * 256 + threadIdx.x;
    int n = idx & (NN - 1);
    int r = idx >> 13;
    int b = r >> 3;
    int g = r & 7;
    z0[idx] = x[((b << 13) + n) * 8 + g];
}

// ---------------------------------------------------------------------------
// Zero-fill z stages 1..3 (atomic accumulation targets)
// ---------------------------------------------------------------------------
__global__ void zero_kernel(float* __restrict__ p) {
    ((float4*)p)[blockIdx.x * 256 + threadIdx.x] = make_float4(0.f, 0.f, 0.f, 0.f);
}

// ---------------------------------------------------------------------------
// bf16x3 mma.sync GEMM with atomic split-K epilogue:
//   zn[r][n0+m] += sum_{k in chunk sp} S[n0+m][k] * z[r][k]
// A flows through a 4-deep k16 cp.async ring (3 stages in flight); B is
// pre-split to bf16 hi/lo smem once per CTA.
// ---------------------------------------------------------------------------
__global__ void __launch_bounds__(256, 4)
gemm_kernel(const float* __restrict__ A, const float* __restrict__ B,
            float* __restrict__ zn) {
    __shared__ __align__(128) char smA[NBUF * A_STAGE_BYTES];  // 32 KB
    __shared__ __align__(128) char smBH[RR * BROW_BYTES];      // 8 KB
    __shared__ __align__(128) char smBL[RR * BROW_BYTES];      // 8 KB

    const int tid = threadIdx.x;
    const int wid = tid >> 5;
    const int lid = tid & 31;
    const int nb  = blockIdx.x;   // 0..63
    const int sp  = blockIdx.y;   // 0..SPLITK-1
    const int n0  = nb * TN;
    const int m0  = sp * KCHUNK;

    const uint32_t smA_u = (uint32_t)__cvta_generic_to_shared(smA);

    // ---------------- A cp.async mapping (k16 stage = 128 rows x 64B) ------
    const int ar = tid >> 2;              // 0..63 (rows ar, ar+64)
    const int ag = tid & 3;               // 16B granule within 64B row
    const float* Asrc = A + (size_t)(n0 + ar) * NN + m0 + ag * 4;
    const uint32_t a_sw = ((uint32_t)(ag ^ (ar & 3))) << 4;
    const uint32_t ad0 = (uint32_t)ar * 64u + a_sw;
    const uint32_t ad1 = ad0 + 64u * 64u;

#define ISSUE_A(S)                                                              \
    {                                                                           \
        const uint32_t bo = smA_u + (uint32_t)((S) & (NBUF - 1)) * A_STAGE_BYTES; \
        const float* srcp = Asrc + (S) * 16;                                    \
        cp16(bo + ad0, srcp);                                                   \
        cp16(bo + ad1, srcp + (size_t)64 * NN);                                 \
    }

    // prologue: stage 0 first (DRAM starts while we stage B)
    ISSUE_A(0);
    asm volatile("cp.async.commit_group;");

    // ---------------- one-time B staging: fp32 -> bf16 hi/lo smem ----------
    {
        const int row   = tid >> 3;          // 0..31
        const int kbase = (tid & 7) << 3;    // 0..56 step 8
        const float* bp = B + (size_t)row * NN + m0 + kbase;
        const uint32_t ph = ((uint32_t)row & 7u) << 4;   // 16B-granule XOR phase
#pragma unroll
        for (int i = 0; i < 2; i++) {
            const int k = kbase + 64 * i;
            float4 v0 = *(const float4*)(bp + 64 * i);
            float4 v1 = *(const float4*)(bp + 64 * i + 4);
            uint32_t h0, l0, h1, l1, h2, l2, h3, l3;
            split2(v0.x, v0.y, h0, l0);
            split2(v0.z, v0.w, h1, l1);
            split2(v1.x, v1.y, h2, l2);
            split2(v1.z, v1.w, h3, l3);
            uint32_t off = (uint32_t)row * BROW_BYTES + (((uint32_t)k * 2u) ^ ph);
            *(uint4*)(smBH + off) = make_uint4(h0, h1, h2, h3);
            *(uint4*)(smBL + off) = make_uint4(l0, l1, l2, l3);
        }
    }

    // prologue: stages 1, 2
    ISSUE_A(1);
    asm volatile("cp.async.commit_group;");
    ISSUE_A(2);
    asm volatile("cp.async.commit_group;");

    // ---------------- fragment lane mappings --------------------------------
    const int rg = lid >> 2;            // 0..7
    const int qh = (lid & 3) >> 1;      // granule low bit
    const uint32_t qb = (uint32_t)(lid & 1) * 8u;

    const int brow0 = ((lid >> 4) << 3) + (lid & 7);   // n-tiles 0/1
    const int brow1 = 16 + brow0;                      // n-tiles 2/3
    const int bhalf = (lid >> 3) & 1;
    const uint32_t smbh = (uint32_t)__cvta_generic_to_shared(smBH);
    const uint32_t smbl = (uint32_t)__cvta_generic_to_shared(smBL);
    const uint32_t bo0base = (uint32_t)brow0 * BROW_BYTES;
    const uint32_t bo1base = (uint32_t)brow1 * BROW_BYTES;
    const uint32_t bph0 = ((uint32_t)brow0 & 7u) << 4;
    const uint32_t bph1 = ((uint32_t)brow1 & 7u) << 4;

    const int arow_lo = 16 * wid + rg;       // thread's M rows (and +8)

    float c[4][4];
#pragma unroll
    for (int j = 0; j < 4; j++)
#pragma unroll
        for (int e = 0; e < 4; e++) c[j][e] = 0.0f;

#pragma unroll
    for (int s = 0; s < NSTG16; s++) {
        // all groups <= s complete (3+s committed, keep 2 newest pending)
        asm volatile("cp.async.wait_group 2;" ::: "memory");
        __syncthreads();   // A(s) visible; compute(s-1) done block-wide

        // keep the commit-per-iteration invariant (empty groups complete fast)
        if (s + 3 < NSTG16) ISSUE_A(s + 3);
        asm volatile("cp.async.commit_group;");

        const uint32_t abuf = smA_u + (uint32_t)(s & (NBUF - 1)) * A_STAGE_BYTES;
        const uint32_t a_row_off = abuf + (uint32_t)arow_lo * 64u;

        // A fragments via swizzled LDS.64: granules qh (k0-7), qh+2 (k8-15)
        const uint32_t g0 = (uint32_t)qh;
        const uint32_t g2 = g0 + 2u;
        const uint32_t x0 = ((g0 ^ (uint32_t)(arow_lo & 3)) << 4) + qb;
        const uint32_t x2 = ((g2 ^ (uint32_t)(arow_lo & 3)) << 4) + qb;
        float2 fa0 = lds64(a_row_off + x0);
        float2 fa1 = lds64(a_row_off + 8u * 64u + x0);
        float2 fa2 = lds64(a_row_off + x2);
        float2 fa3 = lds64(a_row_off + 8u * 64u + x2);

        // B fragments from smem (hi + lo), swizzled ldmatrix
        const uint32_t kb = (uint32_t)(s * 32 + bhalf * 16);
        const uint32_t o0 = bo0base + (kb ^ bph0);
        const uint32_t o1 = bo1base + (kb ^ bph1);
        uint32_t bh[8], bl[8];
        ldsm4(bh[0], bh[1], bh[2], bh[3], smbh + o0);
        ldsm4(bh[4], bh[5], bh[6], bh[7], smbh + o1);
        ldsm4(bl[0], bl[1], bl[2], bl[3], smbl + o0);
        ldsm4(bl[4], bl[5], bl[6], bl[7], smbl + o1);

        // A convert
        uint32_t ah[4], al[4];
        split2(fa0.x, fa0.y, ah[0], al[0]);
        split2(fa1.x, fa1.y, ah[1], al[1]);
        split2(fa2.x, fa2.y, ah[2], al[2]);
        split2(fa3.x, fa3.y, ah[3], al[3]);

        // 12 MMAs: hi*hi + hi*lo + lo*hi
#pragma unroll
        for (int j = 0; j < 4; j++) {
            mma16816(c[j][0], c[j][1], c[j][2], c[j][3],
                     ah[0], ah[1], ah[2], ah[3], bh[2 * j], bh[2 * j + 1]);
            mma16816(c[j][0], c[j][1], c[j][2], c[j][3],
                     ah[0], ah[1], ah[2], ah[3], bl[2 * j], bl[2 * j + 1]);
            mma16816(c[j][0], c[j][1], c[j][2], c[j][3],
                     al[0], al[1], al[2], al[3], bh[2 * j], bh[2 * j + 1]);
        }
    }
#undef ISSUE_A

    // atomic split-K epilogue: accumulate into zn[r][n]
    const int kc = (lid & 3) << 1;
    const int mg = n0 + arow_lo;
#pragma unroll
    for (int j = 0; j < 4; j++) {
        int r = 8 * j + kc;
        float* p0 = zn + (size_t)r * NN + mg;
        float* p1 = zn + (size_t)(r + 1) * NN + mg;
        atomicAdd(p0, c[j][0]);
        atomicAdd(p1, c[j][1]);
        atomicAdd(p0 + 8, c[j][2]);
        atomicAdd(p1 + 8, c[j][3]);
    }
}

// ---------------------------------------------------------------------------
// Final projection (torch-faithful raw-reshape mapping)
// ---------------------------------------------------------------------------
__global__ void final_kernel(const float* __restrict__ z, const float* __restrict__ W,
                             const float* __restrict__ bias, float* __restrict__ y) {
    __shared__ float Ws[256];
    __shared__ float bs[8];
    int t = threadIdx.x;
    Ws[t] = W[t];
    if (t < 8) bs[t] = bias[t];
    __syncthreads();

    int idx = blockIdx.x * 256 + t;
    int n = idx & (NN - 1);
    int b = idx >> 13;
    int k0 = n >> 11;
    int g0 = (n >> 8) & 7;
    const float* zp = z + ((size_t)(k0 * RR + b * 8 + g0) << 13) + ((n & 255) << 5);

    float bb = bs[n >> 10];
    float acc[8];
#pragma unroll
    for (int f = 0; f < 8; f++) acc[f] = bb;

#pragma unroll
    for (int jq = 0; jq < 8; jq++) {
        float4 zv = *(const float4*)(zp + 4 * jq);
#pragma unroll
        for (int e = 0; e < 4; e++) {
            float zs = (e == 0) ? zv.x : (e == 1) ? zv.y : (e == 2) ? zv.z : zv.w;
            int j = 4 * jq + e;
#pragma unroll
            for (int f = 0; f < 8; f++) acc[f] += zs * Ws[8 * j + f];
        }
    }

    float4* yo = (float4*)(y + (size_t)idx * 8);
    yo[0] = make_float4(acc[0], acc[1], acc[2], acc[3]);
    yo[1] = make_float4(acc[4], acc[5], acc[6], acc[7]);
}

// ---------------------------------------------------------------------------
extern "C" void kernel_launch(void* const* d_in, const int* in_sizes, int n_in,
                              void* d_out, int out_size) {
    const float* x    = (const float*)d_in[0];
    const float* S    = (const float*)d_in[1];
    const float* W    = (const float*)d_in[2];
    const float* bias = (const float*)d_in[3];
    float* y = (float*)d_out;

    float* zbuf;
    cudaGetSymbolAddress((void**)&zbuf, g_z);

    transpose_kernel<<<1024, 256>>>(x, zbuf);
    // zero z stages 1..3 (3 * RR * NN floats = 196608 float4)
    zero_kernel<<<768, 256>>>(zbuf + RR * NN);

    for (int k = 0; k < 3; k++) {
        gemm_kernel<<<dim3(64, SPLITK), 256>>>(S + (size_t)k * NN * NN,
                                               zbuf + (size_t)k * RR * NN,
                                               zbuf + (size_t)(k + 1) * RR * NN);
    }

    final_kernel<<<128, 256>>>(zbuf, W, bias, y);
}

// round 13
// speedup vs baseline: 1.3450x; 1.0134x over previous
#include <cuda_runtime.h>
#include <cuda_bf16.h>
#include <cstdint>

// Problem constants
#define NN 8192
#define RR 32
#define TN 128                    // M-tile per block
#define SPLITK 64
#define KCHUNK (NN / SPLITK)      // 128
#define NSTG16 (KCHUNK / 16)      // 8 k16 stages
#define NBUF 4                    // A ring buffers

// Scratch: z stages only (split-K reduced atomically into z)
__device__ float g_z[4 * RR * NN];          // z stages [k][r][n]

// B smem row: 128 k * 2B = 256 bytes, XOR-16B swizzle by (row&7)
#define BROW_BYTES 256
#define A_STAGE_BYTES (TN * 64)   // 8 KB per k16 buffer

__device__ __forceinline__ uint32_t cvt_bf16x2(float hi, float lo) {
    uint32_t r;
    asm("cvt.rn.bf16x2.f32 %0,%1,%2;" : "=r"(r) : "f"(hi), "f"(lo));
    return r;
}
// split 2 fp32 -> packed bf16 hi-pair and lo-pair (element x in low half)
__device__ __forceinline__ void split2(float x, float y, uint32_t& w, uint32_t& l) {
    w = cvt_bf16x2(y, x);
    float h0 = __uint_as_float(w << 16);
    float h1 = __uint_as_float(w & 0xFFFF0000u);
    l = cvt_bf16x2(y - h1, x - h0);
}
__device__ __forceinline__ void ldsm4(uint32_t& r0, uint32_t& r1, uint32_t& r2,
                                      uint32_t& r3, uint32_t a) {
    asm volatile("ldmatrix.sync.aligned.m8n8.x4.shared.b16 {%0,%1,%2,%3},[%4];"
                 : "=r"(r0), "=r"(r1), "=r"(r2), "=r"(r3) : "r"(a));
}
__device__ __forceinline__ void mma16816(float& c0, float& c1, float& c2, float& c3,
                                         uint32_t a0, uint32_t a1, uint32_t a2, uint32_t a3,
                                         uint32_t b0, uint32_t b1) {
    asm volatile(
        "mma.sync.aligned.m16n8k16.row.col.f32.bf16.bf16.f32 "
        "{%0,%1,%2,%3},{%4,%5,%6,%7},{%8,%9},{%0,%1,%2,%3};"
        : "+f"(c0), "+f"(c1), "+f"(c2), "+f"(c3)
        : "r"(a0), "r"(a1), "r"(a2), "r"(a3), "r"(b0), "r"(b1));
}
__device__ __forceinline__ void cp16(uint32_t dst, const void* src) {
    asm volatile("cp.async.cg.shared.global [%0], [%1], 16;" :: "r"(dst), "l"(src));
}
__device__ __forceinline__ float2 lds64(uint32_t addr) {
    float2 v;
    asm volatile("ld.shared.v2.f32 {%0,%1},[%2];" : "=f"(v.x), "=f"(v.y) : "r"(addr));
    return v;
}

// ---------------------------------------------------------------------------
// Stage 0: transpose x[B,N,G] -> z0[r][n], r = b*8+g
// ---------------------------------------------------------------------------
__global__ void transpose_kernel(const float* __restrict__ x, float* __restrict__ z0) {
    int idx = blockIdx.x * 256 + threadIdx.x;
    int n = idx & (NN - 1);
    int r = idx >> 13;
    int b = r >> 3;
    int g = r & 7;
    z0[idx] = x[((b << 13) + n) * 8 + g];
}

// ---------------------------------------------------------------------------
// Zero-fill z stages 1..3 (atomic accumulation targets)
// ---------------------------------------------------------------------------
__global__ void zero_kernel(float* __restrict__ p) {
    ((float4*)p)[blockIdx.x * 256 + threadIdx.x] = make_float4(0.f, 0.f, 0.f, 0.f);
}

// ---------------------------------------------------------------------------
// bf16x3 mma.sync GEMM with staged, coalesced red.v2 split-K epilogue:
//   zn[r][n0+m] += sum_{k in chunk sp} S[n0+m][k] * z[r][k]
// A: 4-deep k16 cp.async ring (3 stages in flight). B: bf16 hi/lo smem once.
// Epilogue: c-tile staged to smem, then coalesced red.global.add.v2.f32.
// ---------------------------------------------------------------------------
__global__ void __launch_bounds__(256, 4)
gemm_kernel(const float* __restrict__ A, const float* __restrict__ B,
            float* __restrict__ zn) {
    __shared__ __align__(128) char smA[NBUF * A_STAGE_BYTES];  // 32 KB (ring; reused as c-stage)
    __shared__ __align__(128) char smBH[RR * BROW_BYTES];      // 8 KB
    __shared__ __align__(128) char smBL[RR * BROW_BYTES];      // 8 KB

    const int tid = threadIdx.x;
    const int wid = tid >> 5;
    const int lid = tid & 31;
    const int nb  = blockIdx.x;   // 0..63
    const int sp  = blockIdx.y;   // 0..SPLITK-1
    const int n0  = nb * TN;
    const int m0  = sp * KCHUNK;

    const uint32_t smA_u = (uint32_t)__cvta_generic_to_shared(smA);

    // ---------------- A cp.async mapping (k16 stage = 128 rows x 64B) ------
    const int ar = tid >> 2;              // 0..63 (rows ar, ar+64)
    const int ag = tid & 3;               // 16B granule within 64B row
    const float* Asrc = A + (size_t)(n0 + ar) * NN + m0 + ag * 4;
    const uint32_t a_sw = ((uint32_t)(ag ^ (ar & 3))) << 4;
    const uint32_t ad0 = (uint32_t)ar * 64u + a_sw;
    const uint32_t ad1 = ad0 + 64u * 64u;

#define ISSUE_A(S)                                                              \
    {                                                                           \
        const uint32_t bo = smA_u + (uint32_t)((S) & (NBUF - 1)) * A_STAGE_BYTES; \
        const float* srcp = Asrc + (S) * 16;                                    \
        cp16(bo + ad0, srcp);                                                   \
        cp16(bo + ad1, srcp + (size_t)64 * NN);                                 \
    }

    // prologue: stage 0 first (DRAM starts while we stage B)
    ISSUE_A(0);
    asm volatile("cp.async.commit_group;");

    // ---------------- one-time B staging: fp32 -> bf16 hi/lo smem ----------
    {
        const int row   = tid >> 3;          // 0..31
        const int kbase = (tid & 7) << 3;    // 0..56 step 8
        const float* bp = B + (size_t)row * NN + m0 + kbase;
        const uint32_t ph = ((uint32_t)row & 7u) << 4;   // 16B-granule XOR phase
#pragma unroll
        for (int i = 0; i < 2; i++) {
            const int k = kbase + 64 * i;
            float4 v0 = *(const float4*)(bp + 64 * i);
            float4 v1 = *(const float4*)(bp + 64 * i + 4);
            uint32_t h0, l0, h1, l1, h2, l2, h3, l3;
            split2(v0.x, v0.y, h0, l0);
            split2(v0.z, v0.w, h1, l1);
            split2(v1.x, v1.y, h2, l2);
            split2(v1.z, v1.w, h3, l3);
            uint32_t off = (uint32_t)row * BROW_BYTES + (((uint32_t)k * 2u) ^ ph);
            *(uint4*)(smBH + off) = make_uint4(h0, h1, h2, h3);
            *(uint4*)(smBL + off) = make_uint4(l0, l1, l2, l3);
        }
    }

    // prologue: stages 1, 2
    ISSUE_A(1);
    asm volatile("cp.async.commit_group;");
    ISSUE_A(2);
    asm volatile("cp.async.commit_group;");

    // ---------------- fragment lane mappings --------------------------------
    const int rg = lid >> 2;            // 0..7
    const int qh = (lid & 3) >> 1;      // granule low bit
    const uint32_t qb = (uint32_t)(lid & 1) * 8u;

    const int brow0 = ((lid >> 4) << 3) + (lid & 7);   // n-tiles 0/1
    const int brow1 = 16 + brow0;                      // n-tiles 2/3
    const int bhalf = (lid >> 3) & 1;
    const uint32_t smbh = (uint32_t)__cvta_generic_to_shared(smBH);
    const uint32_t smbl = (uint32_t)__cvta_generic_to_shared(smBL);
    const uint32_t bo0base = (uint32_t)brow0 * BROW_BYTES;
    const uint32_t bo1base = (uint32_t)brow1 * BROW_BYTES;
    const uint32_t bph0 = ((uint32_t)brow0 & 7u) << 4;
    const uint32_t bph1 = ((uint32_t)brow1 & 7u) << 4;

    const int arow_lo = 16 * wid + rg;       // thread's M rows (and +8)

    float c[4][4];
#pragma unroll
    for (int j = 0; j < 4; j++)
#pragma unroll
        for (int e = 0; e < 4; e++) c[j][e] = 0.0f;

#pragma unroll
    for (int s = 0; s < NSTG16; s++) {
        // all groups <= s complete (3+s committed, keep 2 newest pending)
        asm volatile("cp.async.wait_group 2;" ::: "memory");
        __syncthreads();   // A(s) visible; compute(s-1) done block-wide

        // keep the commit-per-iteration invariant (empty groups complete fast)
        if (s + 3 < NSTG16) ISSUE_A(s + 3);
        asm volatile("cp.async.commit_group;");

        const uint32_t abuf = smA_u + (uint32_t)(s & (NBUF - 1)) * A_STAGE_BYTES;
        const uint32_t a_row_off = abuf + (uint32_t)arow_lo * 64u;

        // A fragments via swizzled LDS.64: granules qh (k0-7), qh+2 (k8-15)
        const uint32_t g0 = (uint32_t)qh;
        const uint32_t g2 = g0 + 2u;
        const uint32_t x0 = ((g0 ^ (uint32_t)(arow_lo & 3)) << 4) + qb;
        const uint32_t x2 = ((g2 ^ (uint32_t)(arow_lo & 3)) << 4) + qb;
        float2 fa0 = lds64(a_row_off + x0);
        float2 fa1 = lds64(a_row_off + 8u * 64u + x0);
        float2 fa2 = lds64(a_row_off + x2);
        float2 fa3 = lds64(a_row_off + 8u * 64u + x2);

        // B fragments from smem (hi + lo), swizzled ldmatrix
        const uint32_t kb = (uint32_t)(s * 32 + bhalf * 16);
        const uint32_t o0 = bo0base + (kb ^ bph0);
        const uint32_t o1 = bo1base + (kb ^ bph1);
        uint32_t bh[8], bl[8];
        ldsm4(bh[0], bh[1], bh[2], bh[3], smbh + o0);
        ldsm4(bh[4], bh[5], bh[6], bh[7], smbh + o1);
        ldsm4(bl[0], bl[1], bl[2], bl[3], smbl + o0);
        ldsm4(bl[4], bl[5], bl[6], bl[7], smbl + o1);

        // A convert
        uint32_t ah[4], al[4];
        split2(fa0.x, fa0.y, ah[0], al[0]);
        split2(fa1.x, fa1.y, ah[1], al[1]);
        split2(fa2.x, fa2.y, ah[2], al[2]);
        split2(fa3.x, fa3.y, ah[3], al[3]);

        // 12 MMAs: hi*hi + hi*lo + lo*hi
#pragma unroll
        for (int j = 0; j < 4; j++) {
            mma16816(c[j][0], c[j][1], c[j][2], c[j][3],
                     ah[0], ah[1], ah[2], ah[3], bh[2 * j], bh[2 * j + 1]);
            mma16816(c[j][0], c[j][1], c[j][2], c[j][3],
                     ah[0], ah[1], ah[2], ah[3], bl[2 * j], bl[2 * j + 1]);
            mma16816(c[j][0], c[j][1], c[j][2], c[j][3],
                     al[0], al[1], al[2], al[3], bh[2 * j], bh[2 * j + 1]);
        }
    }
#undef ISSUE_A

    // ---------------- epilogue: stage c-tile to smem, coalesced red.v2 ------
    // c-tile is [32 r][128 m]; smem rows padded to 132 floats (528B, 16B-aligned;
    // STS bank = (4r+col)%32 -> conflict-free for the fragment pattern).
    __syncthreads();   // ring no longer needed
    float* cstage = (float*)smA;
    {
        const int kc = (lid & 3) << 1;
        const int mloc = arow_lo;     // 16*wid + rg
#pragma unroll
        for (int j = 0; j < 4; j++) {
            int r = 8 * j + kc;
            cstage[r * 132 + mloc]           = c[j][0];
            cstage[(r + 1) * 132 + mloc]     = c[j][1];
            cstage[r * 132 + mloc + 8]       = c[j][2];
            cstage[(r + 1) * 132 + mloc + 8] = c[j][3];
        }
    }
    __syncthreads();
#pragma unroll
    for (int p = 0; p < 8; p++) {
        int idx = tid + 256 * p;        // 0..2047 float2 slots
        int r  = idx >> 6;              // 0..31
        int ch = (idx & 63) * 2;        // col 0..126 step 2
        float2 v = *(const float2*)(cstage + r * 132 + ch);
        float* dst = zn + (size_t)r * NN + n0 + ch;
        asm volatile("red.global.add.v2.f32 [%0], {%1, %2};"
                     :: "l"(dst), "f"(v.x), "f"(v.y) : "memory");
    }
}

// ---------------------------------------------------------------------------
// Final projection (torch-faithful raw-reshape mapping)
// ---------------------------------------------------------------------------
__global__ void final_kernel(const float* __restrict__ z, const float* __restrict__ W,
                             const float* __restrict__ bias, float* __restrict__ y) {
    __shared__ float Ws[256];
    __shared__ float bs[8];
    int t = threadIdx.x;
    Ws[t] = W[t];
    if (t < 8) bs[t] = bias[t];
    __syncthreads();

    int idx = blockIdx.x * 256 + t;
    int n = idx & (NN - 1);
    int b = idx >> 13;
    int k0 = n >> 11;
    int g0 = (n >> 8) & 7;
    const float* zp = z + ((size_t)(k0 * RR + b * 8 + g0) << 13) + ((n & 255) << 5);

    float bb = bs[n >> 10];
    float acc[8];
#pragma unroll
    for (int f = 0; f < 8; f++) acc[f] = bb;

#pragma unroll
    for (int jq = 0; jq < 8; jq++) {
        float4 zv = *(const float4*)(zp + 4 * jq);
#pragma unroll
        for (int e = 0; e < 4; e++) {
            float zs = (e == 0) ? zv.x : (e == 1) ? zv.y : (e == 2) ? zv.z : zv.w;
            int j = 4 * jq + e;
#pragma unroll
            for (int f = 0; f < 8; f++) acc[f] += zs * Ws[8 * j + f];
        }
    }

    float4* yo = (float4*)(y + (size_t)idx * 8);
    yo[0] = make_float4(acc[0], acc[1], acc[2], acc[3]);
    yo[1] = make_float4(acc[4], acc[5], acc[6], acc[7]);
}

// ---------------------------------------------------------------------------
extern "C" void kernel_launch(void* const* d_in, const int* in_sizes, int n_in,
                              void* d_out, int out_size) {
    const float* x    = (const float*)d_in[0];
    const float* S    = (const float*)d_in[1];
    const float* W    = (const float*)d_in[2];
    const float* bias = (const float*)d_in[3];
    float* y = (float*)d_out;

    float* zbuf;
    cudaGetSymbolAddress((void**)&zbuf, g_z);

    transpose_kernel<<<1024, 256>>>(x, zbuf);
    // zero z stages 1..3 (3 * RR * NN floats = 196608 float4)
    zero_kernel<<<768, 256>>>(zbuf + RR * NN);

    for (int k = 0; k < 3; k++) {
        gemm_kernel<<<dim3(64, SPLITK), 256>>>(S + (size_t)k * NN * NN,
                                               zbuf + (size_t)k * RR * NN,
                                               zbuf + (size_t)(k + 1) * RR * NN);
    }

    final_kernel<<<128, 256>>>(zbuf, W, bias, y);
}

// round 14
// speedup vs baseline: 1.4121x; 1.0499x over previous
#include <cuda_runtime.h>
#include <cuda_bf16.h>
#include <cstdint>

// Problem constants
#define NN 8192
#define RR 32
#define TN 128                    // M-tile per block
#define SPLITK 64
#define KCHUNK (NN / SPLITK)      // 128
#define NSTG16 (KCHUNK / 16)      // 8 k16 stages
#define NBUF 4                    // A ring buffers
#define THREADS 128               // 4 warps; warp tile = 32M x 32N

// Scratch: z stages only (split-K reduced atomically into z)
__device__ float g_z[4 * RR * NN];          // z stages [k][r][n]

// B smem row: 128 k * 2B = 256 bytes, XOR-16B swizzle by (row&7)
#define BROW_BYTES 256
#define A_STAGE_BYTES (TN * 64)   // 8 KB per k16 buffer

__device__ __forceinline__ uint32_t cvt_bf16x2(float hi, float lo) {
    uint32_t r;
    asm("cvt.rn.bf16x2.f32 %0,%1,%2;" : "=r"(r) : "f"(hi), "f"(lo));
    return r;
}
// split 2 fp32 -> packed bf16 hi-pair and lo-pair (element x in low half)
__device__ __forceinline__ void split2(float x, float y, uint32_t& w, uint32_t& l) {
    w = cvt_bf16x2(y, x);
    float h0 = __uint_as_float(w << 16);
    float h1 = __uint_as_float(w & 0xFFFF0000u);
    l = cvt_bf16x2(y - h1, x - h0);
}
__device__ __forceinline__ void ldsm4(uint32_t& r0, uint32_t& r1, uint32_t& r2,
                                      uint32_t& r3, uint32_t a) {
    asm volatile("ldmatrix.sync.aligned.m8n8.x4.shared.b16 {%0,%1,%2,%3},[%4];"
                 : "=r"(r0), "=r"(r1), "=r"(r2), "=r"(r3) : "r"(a));
}
__device__ __forceinline__ void mma16816(float& c0, float& c1, float& c2, float& c3,
                                         uint32_t a0, uint32_t a1, uint32_t a2, uint32_t a3,
                                         uint32_t b0, uint32_t b1) {
    asm volatile(
        "mma.sync.aligned.m16n8k16.row.col.f32.bf16.bf16.f32 "
        "{%0,%1,%2,%3},{%4,%5,%6,%7},{%8,%9},{%0,%1,%2,%3};"
        : "+f"(c0), "+f"(c1), "+f"(c2), "+f"(c3)
        : "r"(a0), "r"(a1), "r"(a2), "r"(a3), "r"(b0), "r"(b1));
}
__device__ __forceinline__ void cp16(uint32_t dst, const void* src) {
    asm volatile("cp.async.cg.shared.global [%0], [%1], 16;" :: "r"(dst), "l"(src));
}
__device__ __forceinline__ float2 lds64(uint32_t addr) {
    float2 v;
    asm volatile("ld.shared.v2.f32 {%0,%1},[%2];" : "=f"(v.x), "=f"(v.y) : "r"(addr));
    return v;
}

// ---------------------------------------------------------------------------
// Stage 0: transpose x[B,N,G] -> z0[r][n], r = b*8+g
// ---------------------------------------------------------------------------
__global__ void transpose_kernel(const float* __restrict__ x, float* __restrict__ z0) {
    int idx = blockIdx.x * 256 + threadIdx.x;
    int n = idx & (NN - 1);
    int r = idx >> 13;
    int b = r >> 3;
    int g = r & 7;
    z0[idx] = x[((b << 13) + n) * 8 + g];
}

// ---------------------------------------------------------------------------
// Zero-fill z stages 1..3 (atomic accumulation targets)
// ---------------------------------------------------------------------------
__global__ void zero_kernel(float* __restrict__ p) {
    ((float4*)p)[blockIdx.x * 256 + threadIdx.x] = make_float4(0.f, 0.f, 0.f, 0.f);
}

// ---------------------------------------------------------------------------
// bf16x3 mma.sync GEMM, 4 warps, warp tile 32M x 32N (halves B-LDSM traffic):
//   zn[r][n0+m] += sum_{k in chunk sp} S[n0+m][k] * z[r][k]
// A: 4-deep k16 cp.async ring. B: bf16 hi/lo smem once per CTA.
// Epilogue: c-tile staged to smem, coalesced red.global.add.v2.f32.
// ---------------------------------------------------------------------------
__global__ void __launch_bounds__(THREADS, 4)
gemm_kernel(const float* __restrict__ A, const float* __restrict__ B,
            float* __restrict__ zn) {
    __shared__ __align__(128) char smA[NBUF * A_STAGE_BYTES];  // 32 KB (ring; reused as c-stage)
    __shared__ __align__(128) char smBH[RR * BROW_BYTES];      // 8 KB
    __shared__ __align__(128) char smBL[RR * BROW_BYTES];      // 8 KB

    const int tid = threadIdx.x;
    const int wid = tid >> 5;       // 0..3
    const int lid = tid & 31;
    const int nb  = blockIdx.x;     // 0..63
    const int sp  = blockIdx.y;     // 0..SPLITK-1
    const int n0  = nb * TN;
    const int m0  = sp * KCHUNK;

    const uint32_t smA_u = (uint32_t)__cvta_generic_to_shared(smA);

    // ---------------- A cp.async mapping (k16 stage = 128 rows x 64B) ------
    // 128 threads: 4 rows-groups of 32; each thread copies 4 x 16B.
    const int ar = tid >> 2;              // 0..31 (rows ar + 32p)
    const int ag = tid & 3;               // 16B granule within 64B row
    const float* Asrc = A + (size_t)(n0 + ar) * NN + m0 + ag * 4;
    const uint32_t a_sw = ((uint32_t)(ag ^ (ar & 3))) << 4;
    const uint32_t ad0 = (uint32_t)ar * 64u + a_sw;

#define ISSUE_A(S)                                                              \
    {                                                                           \
        const uint32_t bo = smA_u + (uint32_t)((S) & (NBUF - 1)) * A_STAGE_BYTES; \
        const float* srcp = Asrc + (S) * 16;                                    \
        cp16(bo + ad0,               srcp);                                     \
        cp16(bo + ad0 + 32u * 64u,   srcp + (size_t)32 * NN);                   \
        cp16(bo + ad0 + 64u * 64u,   srcp + (size_t)64 * NN);                   \
        cp16(bo + ad0 + 96u * 64u,   srcp + (size_t)96 * NN);                   \
    }

    // prologue: stage 0 first (DRAM starts while we stage B)
    ISSUE_A(0);
    asm volatile("cp.async.commit_group;");

    // ---------------- one-time B staging: fp32 -> bf16 hi/lo smem ----------
    {
        const int row   = tid >> 2;          // 0..31
        const int kbase = (tid & 3) << 3;    // 0,8,16,24
        const float* bp = B + (size_t)row * NN + m0 + kbase;
        const uint32_t ph = ((uint32_t)row & 7u) << 4;   // 16B-granule XOR phase
#pragma unroll
        for (int i = 0; i < 4; i++) {
            const int k = kbase + 32 * i;
            float4 v0 = *(const float4*)(bp + 32 * i);
            float4 v1 = *(const float4*)(bp + 32 * i + 4);
            uint32_t h0, l0, h1, l1, h2, l2, h3, l3;
            split2(v0.x, v0.y, h0, l0);
            split2(v0.z, v0.w, h1, l1);
            split2(v1.x, v1.y, h2, l2);
            split2(v1.z, v1.w, h3, l3);
            uint32_t off = (uint32_t)row * BROW_BYTES + (((uint32_t)k * 2u) ^ ph);
            *(uint4*)(smBH + off) = make_uint4(h0, h1, h2, h3);
            *(uint4*)(smBL + off) = make_uint4(l0, l1, l2, l3);
        }
    }

    // prologue: stages 1, 2
    ISSUE_A(1);
    asm volatile("cp.async.commit_group;");
    ISSUE_A(2);
    asm volatile("cp.async.commit_group;");

    // ---------------- fragment lane mappings --------------------------------
    const int rg = lid >> 2;            // 0..7
    const int qh = (lid & 3) >> 1;      // granule low bit
    const uint32_t qb = (uint32_t)(lid & 1) * 8u;

    const int brow0 = ((lid >> 4) << 3) + (lid & 7);   // n-tiles 0/1
    const int brow1 = 16 + brow0;                      // n-tiles 2/3
    const int bhalf = (lid >> 3) & 1;
    const uint32_t smbh = (uint32_t)__cvta_generic_to_shared(smBH);
    const uint32_t smbl = (uint32_t)__cvta_generic_to_shared(smBL);
    const uint32_t bo0base = (uint32_t)brow0 * BROW_BYTES;
    const uint32_t bo1base = (uint32_t)brow1 * BROW_BYTES;
    const uint32_t bph0 = ((uint32_t)brow0 & 7u) << 4;
    const uint32_t bph1 = ((uint32_t)brow1 & 7u) << 4;

    // warp owns M rows 32*wid .. 32*wid+31 (two m16 groups)
    const int mrow0 = 32 * wid + rg;          // group 0 rows (and +8)
    // A lds offsets within a row (identical phase for rows rg, rg+8, rg+16, rg+24)
    const uint32_t x0 = (((uint32_t)qh ^ (uint32_t)(mrow0 & 3)) << 4) + qb;
    const uint32_t x2 = ((((uint32_t)qh + 2u) ^ (uint32_t)(mrow0 & 3)) << 4) + qb;

    float c[2][4][4];
#pragma unroll
    for (int h2 = 0; h2 < 2; h2++)
#pragma unroll
        for (int j = 0; j < 4; j++)
#pragma unroll
            for (int e = 0; e < 4; e++) c[h2][j][e] = 0.0f;

#pragma unroll
    for (int s = 0; s < NSTG16; s++) {
        asm volatile("cp.async.wait_group 2;" ::: "memory");
        __syncthreads();   // A(s) visible; compute(s-1) done block-wide

        if (s + 3 < NSTG16) ISSUE_A(s + 3);
        asm volatile("cp.async.commit_group;");

        const uint32_t abuf = smA_u + (uint32_t)(s & (NBUF - 1)) * A_STAGE_BYTES;
        const uint32_t arow_base = abuf + (uint32_t)mrow0 * 64u;

        // B fragments (shared by both m-groups)
        const uint32_t kb = (uint32_t)(s * 32 + bhalf * 16);
        const uint32_t o0 = bo0base + (kb ^ bph0);
        const uint32_t o1 = bo1base + (kb ^ bph1);
        uint32_t bh[8], bl[8];
        ldsm4(bh[0], bh[1], bh[2], bh[3], smbh + o0);
        ldsm4(bh[4], bh[5], bh[6], bh[7], smbh + o1);
        ldsm4(bl[0], bl[1], bl[2], bl[3], smbl + o0);
        ldsm4(bl[4], bl[5], bl[6], bl[7], smbl + o1);

#pragma unroll
        for (int h2 = 0; h2 < 2; h2++) {
            const uint32_t a_row_off = arow_base + (uint32_t)(h2 * 16) * 64u;
            float2 fa0 = lds64(a_row_off + x0);
            float2 fa1 = lds64(a_row_off + 8u * 64u + x0);
            float2 fa2 = lds64(a_row_off + x2);
            float2 fa3 = lds64(a_row_off + 8u * 64u + x2);

            uint32_t ah[4], al[4];
            split2(fa0.x, fa0.y, ah[0], al[0]);
            split2(fa1.x, fa1.y, ah[1], al[1]);
            split2(fa2.x, fa2.y, ah[2], al[2]);
            split2(fa3.x, fa3.y, ah[3], al[3]);

#pragma unroll
            for (int j = 0; j < 4; j++) {
                mma16816(c[h2][j][0], c[h2][j][1], c[h2][j][2], c[h2][j][3],
                         ah[0], ah[1], ah[2], ah[3], bh[2 * j], bh[2 * j + 1]);
                mma16816(c[h2][j][0], c[h2][j][1], c[h2][j][2], c[h2][j][3],
                         ah[0], ah[1], ah[2], ah[3], bl[2 * j], bl[2 * j + 1]);
                mma16816(c[h2][j][0], c[h2][j][1], c[h2][j][2], c[h2][j][3],
                         al[0], al[1], al[2], al[3], bh[2 * j], bh[2 * j + 1]);
            }
        }
    }
#undef ISSUE_A

    // ---------------- epilogue: stage c-tile to smem, coalesced red.v2 ------
    // c-tile [32 r][128 m], rows padded to 132 floats; STS conflict-free
    // (bank = (4kc*... + 16h2 + rg) spans all 32).
    __syncthreads();   // ring no longer needed
    float* cstage = (float*)smA;
    {
        const int kc = (lid & 3) << 1;
#pragma unroll
        for (int h2 = 0; h2 < 2; h2++) {
            const int mloc = 32 * wid + 16 * h2 + rg;
#pragma unroll
            for (int j = 0; j < 4; j++) {
                int r = 8 * j + kc;
                cstage[r * 132 + mloc]           = c[h2][j][0];
                cstage[(r + 1) * 132 + mloc]     = c[h2][j][1];
                cstage[r * 132 + mloc + 8]       = c[h2][j][2];
                cstage[(r + 1) * 132 + mloc + 8] = c[h2][j][3];
            }
        }
    }
    __syncthreads();
#pragma unroll
    for (int p = 0; p < 16; p++) {
        int idx = tid + THREADS * p;    // 0..2047 float2 slots
        int r  = idx >> 6;              // 0..31
        int ch = (idx & 63) * 2;        // col 0..126 step 2
        float2 v = *(const float2*)(cstage + r * 132 + ch);
        float* dst = zn + (size_t)r * NN + n0 + ch;
        asm volatile("red.global.add.v2.f32 [%0], {%1, %2};"
                     :: "l"(dst), "f"(v.x), "f"(v.y) : "memory");
    }
}

// ---------------------------------------------------------------------------
// Final projection (torch-faithful raw-reshape mapping)
// ---------------------------------------------------------------------------
__global__ void final_kernel(const float* __restrict__ z, const float* __restrict__ W,
                             const float* __restrict__ bias, float* __restrict__ y) {
    __shared__ float Ws[256];
    __shared__ float bs[8];
    int t = threadIdx.x;
    Ws[t] = W[t];
    if (t < 8) bs[t] = bias[t];
    __syncthreads();

    int idx = blockIdx.x * 256 + t;
    int n = idx & (NN - 1);
    int b = idx >> 13;
    int k0 = n >> 11;
    int g0 = (n >> 8) & 7;
    const float* zp = z + ((size_t)(k0 * RR + b * 8 + g0) << 13) + ((n & 255) << 5);

    float bb = bs[n >> 10];
    float acc[8];
#pragma unroll
    for (int f = 0; f < 8; f++) acc[f] = bb;

#pragma unroll
    for (int jq = 0; jq < 8; jq++) {
        float4 zv = *(const float4*)(zp + 4 * jq);
#pragma unroll
        for (int e = 0; e < 4; e++) {
            float zs = (e == 0) ? zv.x : (e == 1) ? zv.y : (e == 2) ? zv.z : zv.w;
            int j = 4 * jq + e;
#pragma unroll
            for (int f = 0; f < 8; f++) acc[f] += zs * Ws[8 * j + f];
        }
    }

    float4* yo = (float4*)(y + (size_t)idx * 8);
    yo[0] = make_float4(acc[0], acc[1], acc[2], acc[3]);
    yo[1] = make_float4(acc[4], acc[5], acc[6], acc[7]);
}

// ---------------------------------------------------------------------------
extern "C" void kernel_launch(void* const* d_in, const int* in_sizes, int n_in,
                              void* d_out, int out_size) {
    const float* x    = (const float*)d_in[0];
    const float* S    = (const float*)d_in[1];
    const float* W    = (const float*)d_in[2];
    const float* bias = (const float*)d_in[3];
    float* y = (float*)d_out;

    float* zbuf;
    cudaGetSymbolAddress((void**)&zbuf, g_z);

    transpose_kernel<<<1024, 256>>>(x, zbuf);
    // zero z stages 1..3 (3 * RR * NN floats = 196608 float4)
    zero_kernel<<<768, 256>>>(zbuf + RR * NN);

    for (int k = 0; k < 3; k++) {
        gemm_kernel<<<dim3(64, SPLITK), THREADS>>>(S + (size_t)k * NN * NN,
                                                   zbuf + (size_t)k * RR * NN,
                                                   zbuf + (size_t)(k + 1) * RR * NN);
    }

    final_kernel<<<128, 256>>>(zbuf, W, bias, y);
}